// round 12
// baseline (speedup 1.0000x reference)
#include <cuda_runtime.h>
#include <cuda_bf16.h>
#include <cstdint>

#define DIM     1024
#define BATCH   16384
#define NLAYERS 18

// ---------------- GEMM tiling: BM=64 for wave-quantization fix ----------------
#define BM 64
#define BN 128
#define BK 32                     // bf16 per K-chunk = 64B per row
#define NCHUNK (DIM / BK)         // 32

// smem stage: Ah/Al 64x64B = 4KB each, Wh/Wl 128x64B = 8KB each -> 24KB/stage
#define OFF_AL 4096u
#define OFF_WH 8192u
#define OFF_WL 16384u
#define STAGE  24576u
#define SM_TOTAL (2 * 24576)

// ---------------- static device scratch ----------------
__device__ __align__(16) __nv_bfloat16 g_Wh[NLAYERS * DIM * DIM];
__device__ __align__(16) __nv_bfloat16 g_Wl[NLAYERS * DIM * DIM];
__device__ __align__(16) __nv_bfloat16 g_A0h[BATCH * DIM];
__device__ __align__(16) __nv_bfloat16 g_A0l[BATCH * DIM];
__device__ __align__(16) __nv_bfloat16 g_A1h[BATCH * DIM];
__device__ __align__(16) __nv_bfloat16 g_A1l[BATCH * DIM];
__device__ __align__(16) __nv_bfloat16 g_Rh [BATCH * DIM];
__device__ __align__(16) __nv_bfloat16 g_Rl [BATCH * DIM];

// ---------------- PTX helpers ----------------
__device__ __forceinline__ uint32_t smem_u32(const void* p) {
    uint32_t a;
    asm("{ .reg .u64 t; cvta.to.shared.u64 t, %1; cvt.u32.u64 %0, t; }" : "=r"(a) : "l"(p));
    return a;
}
#define CP_ASYNC16(dst, src) \
    asm volatile("cp.async.cg.shared.global [%0], [%1], 16;\n" :: "r"(dst), "l"(src))
#define CP_COMMIT() asm volatile("cp.async.commit_group;\n" ::: "memory")
#define CP_WAIT1()  asm volatile("cp.async.wait_group 1;\n" ::: "memory")
#define CP_WAIT0()  asm volatile("cp.async.wait_group 0;\n" ::: "memory")

#define LDSM_X4(r0, r1, r2, r3, addr) \
    asm volatile("ldmatrix.sync.aligned.m8n8.x4.shared.b16 {%0,%1,%2,%3}, [%4];\n" \
                 : "=r"(r0), "=r"(r1), "=r"(r2), "=r"(r3) : "r"(addr))

#define MMA4(d, a0, a1, a2, a3, b0, b1) \
    asm volatile("mma.sync.aligned.m16n8k16.row.col.f32.bf16.bf16.f32 " \
                 "{%0,%1,%2,%3},{%4,%5,%6,%7},{%8,%9},{%0,%1,%2,%3};\n" \
                 : "+f"((d)[0]), "+f"((d)[1]), "+f"((d)[2]), "+f"((d)[3]) \
                 : "r"(a0), "r"(a1), "r"(a2), "r"(a3), "r"(b0), "r"(b1))

// packed f32x2 helpers (used in k_prep; proven in R11)
#define PACK2(u, lo, hi) \
    asm volatile("mov.b64 %0, {%1, %2};\n" : "=l"(u) : "f"(lo), "f"(hi))
#define UNPACK2(lo, hi, u) \
    asm volatile("mov.b64 {%0, %1}, %2;\n" : "=f"(lo), "=f"(hi) : "l"(u))
#define FMA2(a, b, c) \
    asm volatile("fma.rn.f32x2 %0, %1, %2, %0;\n" : "+l"(a) : "l"(b), "l"(c))

__device__ __forceinline__ void split1(float v, __nv_bfloat16& h, __nv_bfloat16& l) {
    h = __float2bfloat16(v);
    l = __float2bfloat16(v - __bfloat162float(h));
}

// swizzle for 64B rows: 16B-group g XOR (row & 3) — verified conflict-free (R6/R11)
__device__ __forceinline__ uint32_t swz64(uint32_t row, uint32_t g16) {
    return row * 64u + ((g16 ^ (row & 3u)) << 4);
}

// stage loader: 24KB / 256 threads = 6 cp.async x16B per thread
__device__ __forceinline__ void load_chunk(
    uint32_t st, int c, int tid,
    const char* pAh, const char* pAl, const char* pWh, const char* pWl)
{
    const size_t koff = (size_t)c * 64u;
    // A pair: 512 slots (2 arrays x 64 rows x 4 groups)
#pragma unroll
    for (int i = 0; i < 2; i++) {
        int idx = tid + i * 256;          // 0..511
        int arr = idx >> 8;               // 0 Ah, 1 Al
        int r   = (idx >> 2) & 63;
        int g   = idx & 3;
        const char* base = arr ? pAl : pAh;
        uint32_t dst = st + (uint32_t)arr * 4096u + swz64((uint32_t)r, (uint32_t)g);
        CP_ASYNC16(dst, base + (size_t)r * 2048 + koff + (size_t)(g * 16));
    }
    // W pair: 1024 slots (2 arrays x 128 rows x 4 groups)
#pragma unroll
    for (int i = 0; i < 4; i++) {
        int idx = tid + i * 256;          // 0..1023
        int arr = idx >> 9;               // 0 Wh, 1 Wl
        int r   = (idx >> 2) & 127;
        int g   = idx & 3;
        const char* base = arr ? pWl : pWh;
        uint32_t dst = st + 8192u + (uint32_t)arr * 8192u + swz64((uint32_t)r, (uint32_t)g);
        CP_ASYNC16(dst, base + (size_t)r * 2048 + koff + (size_t)(g * 16));
    }
    CP_COMMIT();
}

// ---------------- fused GEMM layer ----------------
// C[BM,BN] = A[BM,K] * W[BN,K]^T, 3-term bf16 split, fp32 accum. Warp tile 32x32.
// MODE 0: relu(C+bias)->bf16 pair | MODE 1: C+bias+res->bf16 pair | MODE 2: C+bias+res->fp32
template<int MODE>
__global__ void __launch_bounds__(256, 2)
k_gemm(const __nv_bfloat16* __restrict__ Ah, const __nv_bfloat16* __restrict__ Al,
       const __nv_bfloat16* __restrict__ Wh, const __nv_bfloat16* __restrict__ Wl,
       const float* __restrict__ bias,
       __nv_bfloat16* __restrict__ Oh, __nv_bfloat16* __restrict__ Ol,
       const __nv_bfloat16* __restrict__ Rh, const __nv_bfloat16* __restrict__ Rl,
       float* __restrict__ Of)
{
    extern __shared__ char smem[];
    const uint32_t sb = smem_u32(smem);
    const int tid = threadIdx.x, wid = tid >> 5, lane = tid & 31;
    const int Mb = blockIdx.y * BM, Nb = blockIdx.x * BN;
    const int wm = (wid & 1) * 32;          // 2 m-warps
    const int wn = (wid >> 1) * 32;         // 4 n-warps

    const char* pAh = (const char*)(Ah + (size_t)Mb * DIM);
    const char* pAl = (const char*)(Al + (size_t)Mb * DIM);
    const char* pWh = (const char*)(Wh + (size_t)Nb * DIM);
    const char* pWl = (const char*)(Wl + (size_t)Nb * DIM);

    const int l7  = lane & 7;
    const int l15 = lane & 15;
    const int lhi = lane >> 4;              // 0/1
    const int lb8 = ((lane >> 3) & 1) << 3;

    uint32_t adA[2][2], adB[2][2];
#pragma unroll
    for (int kk = 0; kk < 2; kk++) {
#pragma unroll
        for (int mi = 0; mi < 2; mi++) {
            uint32_t r = (uint32_t)(wm + mi * 16 + l15);
            adA[kk][mi] = swz64(r, (uint32_t)(2 * kk + lhi));
        }
#pragma unroll
        for (int j = 0; j < 2; j++) {
            uint32_t r = (uint32_t)(wn + j * 16 + l7 + lb8);
            adB[kk][j] = swz64(r, (uint32_t)(2 * kk + lhi));
        }
    }

    float acc[2][4][4];
#pragma unroll
    for (int mi = 0; mi < 2; mi++)
#pragma unroll
        for (int ni = 0; ni < 4; ni++)
#pragma unroll
            for (int k = 0; k < 4; k++) acc[mi][ni][k] = 0.f;

    load_chunk(sb, 0, tid, pAh, pAl, pWh, pWl);

#pragma unroll 1
    for (int c = 0; c < NCHUNK; c++) {
        const uint32_t st = sb + (uint32_t)(c & 1) * STAGE;
        if (c + 1 < NCHUNK) {
            load_chunk(sb + (uint32_t)((c + 1) & 1) * STAGE, c + 1, tid, pAh, pAl, pWh, pWl);
            CP_WAIT1();
        } else {
            CP_WAIT0();
        }
        __syncthreads();

        const uint32_t stAh = st, stAl = st + OFF_AL, stWh = st + OFF_WH, stWl = st + OFF_WL;
#pragma unroll
        for (int kk = 0; kk < 2; kk++) {
            uint32_t aH[2][4], bH[2][4];
#pragma unroll
            for (int mi = 0; mi < 2; mi++)
                LDSM_X4(aH[mi][0], aH[mi][1], aH[mi][2], aH[mi][3], stAh + adA[kk][mi]);
#pragma unroll
            for (int j = 0; j < 2; j++)
                LDSM_X4(bH[j][0], bH[j][1], bH[j][2], bH[j][3], stWh + adB[kk][j]);
            // T1: Ah*Wh
#pragma unroll
            for (int mi = 0; mi < 2; mi++)
#pragma unroll
                for (int j = 0; j < 2; j++) {
                    MMA4(acc[mi][2 * j],     aH[mi][0], aH[mi][1], aH[mi][2], aH[mi][3], bH[j][0], bH[j][2]);
                    MMA4(acc[mi][2 * j + 1], aH[mi][0], aH[mi][1], aH[mi][2], aH[mi][3], bH[j][1], bH[j][3]);
                }
            // T3: Al*Wh (bH live)
            {
                uint32_t aL[2][4];
#pragma unroll
                for (int mi = 0; mi < 2; mi++)
                    LDSM_X4(aL[mi][0], aL[mi][1], aL[mi][2], aL[mi][3], stAl + adA[kk][mi]);
#pragma unroll
                for (int mi = 0; mi < 2; mi++)
#pragma unroll
                    for (int j = 0; j < 2; j++) {
                        MMA4(acc[mi][2 * j],     aL[mi][0], aL[mi][1], aL[mi][2], aL[mi][3], bH[j][0], bH[j][2]);
                        MMA4(acc[mi][2 * j + 1], aL[mi][0], aL[mi][1], aL[mi][2], aL[mi][3], bH[j][1], bH[j][3]);
                    }
            }
            // T2: Ah*Wl (aH live)
            {
                uint32_t bL[2][4];
#pragma unroll
                for (int j = 0; j < 2; j++)
                    LDSM_X4(bL[j][0], bL[j][1], bL[j][2], bL[j][3], stWl + adB[kk][j]);
#pragma unroll
                for (int mi = 0; mi < 2; mi++)
#pragma unroll
                    for (int j = 0; j < 2; j++) {
                        MMA4(acc[mi][2 * j],     aH[mi][0], aH[mi][1], aH[mi][2], aH[mi][3], bL[j][0], bL[j][2]);
                        MMA4(acc[mi][2 * j + 1], aH[mi][0], aH[mi][1], aH[mi][2], aH[mi][3], bL[j][1], bL[j][3]);
                    }
            }
        }
        __syncthreads();
    }

    // ---- epilogue (verified fragment layout) ----
    auto emit = [&](int r, int c, float v0, float v1) {
        size_t off = (size_t)r * DIM + c;
        if (MODE >= 1) {
            __nv_bfloat162 rh2 = *reinterpret_cast<const __nv_bfloat162*>(Rh + off);
            __nv_bfloat162 rl2 = *reinterpret_cast<const __nv_bfloat162*>(Rl + off);
            v0 += __bfloat162float(rh2.x) + __bfloat162float(rl2.x);
            v1 += __bfloat162float(rh2.y) + __bfloat162float(rl2.y);
        }
        if (MODE == 0) { v0 = fmaxf(v0, 0.f); v1 = fmaxf(v1, 0.f); }
        if (MODE == 2) {
            *reinterpret_cast<float2*>(Of + off) = make_float2(v0, v1);
        } else {
            __nv_bfloat16 h0, l0, h1, l1;
            split1(v0, h0, l0); split1(v1, h1, l1);
            __nv_bfloat162 H; H.x = h0; H.y = h1;
            __nv_bfloat162 L; L.x = l0; L.y = l1;
            *reinterpret_cast<__nv_bfloat162*>(Oh + off) = H;
            *reinterpret_cast<__nv_bfloat162*>(Ol + off) = L;
        }
    };

    const int g  = lane >> 2;
    const int tg = lane & 3;
#pragma unroll
    for (int mi = 0; mi < 2; mi++) {
#pragma unroll
        for (int ni = 0; ni < 4; ni++) {
            int r0 = Mb + wm + mi * 16 + g;
            int c0 = Nb + wn + ni * 8 + tg * 2;
            float b0 = __ldg(bias + c0), b1 = __ldg(bias + c0 + 1);
            emit(r0,     c0, acc[mi][ni][0] + b0, acc[mi][ni][1] + b1);
            emit(r0 + 8, c0, acc[mi][ni][2] + b0, acc[mi][ni][3] + b1);
        }
    }
}

// ---------------- split input x into (hi,lo) pair in R only ----------------
__global__ void k_split(const float* __restrict__ x,
                        __nv_bfloat16* __restrict__ rh, __nv_bfloat16* __restrict__ rl) {
    int i4 = blockIdx.x * blockDim.x + threadIdx.x;
    float4 v = reinterpret_cast<const float4*>(x)[i4];
    __nv_bfloat16 h0,h1,h2,h3,l0,l1,l2,l3;
    split1(v.x,h0,l0); split1(v.y,h1,l1); split1(v.z,h2,l2); split1(v.w,h3,l3);
    __nv_bfloat162 H0; H0.x=h0; H0.y=h1;
    __nv_bfloat162 H1; H1.x=h2; H1.y=h3;
    __nv_bfloat162 L0; L0.x=l0; L0.y=l1;
    __nv_bfloat162 L1; L1.x=l2; L1.y=l3;
    __nv_bfloat162* RH = reinterpret_cast<__nv_bfloat162*>(rh);
    __nv_bfloat162* RL = reinterpret_cast<__nv_bfloat162*>(rl);
    int b = i4 * 2;
    RH[b] = H0; RH[b+1] = H1;
    RL[b] = L0; RL[b+1] = L1;
}

// ---------------- dequant + fold LoRA (f32x2, 2 outputs/thread; R11 proven) ----------------
__global__ void __launch_bounds__(256)
k_prep(const int* __restrict__ qw, const float* __restrict__ scale,
       const float* __restrict__ la, const float* __restrict__ lb) {
    int idx2 = blockIdx.x * 256 + threadIdx.x;        // < 18*1024*512
    int l    = idx2 >> 19;
    int rem  = idx2 & 0x7FFFF;
    int o    = rem >> 9;
    int i    = (rem & 511) * 2;

    size_t base = ((size_t)l << 20) + ((size_t)o << 10) + (size_t)i;
    int2 q2 = *reinterpret_cast<const int2*>(qw + base);
    float s = scale[(l << 16) + (o << 6) + (i >> 4)];
    float w0 = ((float)q2.x / 15.0f * 2.0f - 1.0f) * s;
    float w1 = ((float)q2.y / 15.0f * 2.0f - 1.0f) * s;

    const float4* lb4 = reinterpret_cast<const float4*>(lb + l * (DIM * 32) + o * 32);
    float lbv[32];
#pragma unroll
    for (int q = 0; q < 8; q++) {
        float4 v = lb4[q];
        lbv[q * 4]     = v.x; lbv[q * 4 + 1] = v.y;
        lbv[q * 4 + 2] = v.z; lbv[q * 4 + 3] = v.w;
    }

    const float* lar = la + l * (32 * DIM) + i;
    unsigned long long accp;
    PACK2(accp, w0, w1);
#pragma unroll
    for (int r = 0; r < 32; r++) {
        float2 a2 = *reinterpret_cast<const float2*>(lar + (size_t)r * DIM);
        unsigned long long ap, bp;
        PACK2(ap, a2.x, a2.y);
        PACK2(bp, lbv[r], lbv[r]);
        FMA2(accp, bp, ap);
    }
    float r0, r1;
    UNPACK2(r0, r1, accp);

    __nv_bfloat16 h0, l0, h1, l1;
    split1(r0, h0, l0);
    split1(r1, h1, l1);
    __nv_bfloat162 H; H.x = h0; H.y = h1;
    __nv_bfloat162 L; L.x = l0; L.y = l1;
    *reinterpret_cast<__nv_bfloat162*>(g_Wh + base) = H;
    *reinterpret_cast<__nv_bfloat162*>(g_Wl + base) = L;
}

// ---------------- LayerNorm: reads pair, writes pair to ONE destination ----------------
__device__ __forceinline__ float blockSum256(float v, float* red) {
#pragma unroll
    for (int o = 16; o > 0; o >>= 1) v += __shfl_xor_sync(0xffffffffu, v, o);
    int w = threadIdx.x >> 5;
    if ((threadIdx.x & 31) == 0) red[w] = v;
    __syncthreads();
    float t = 0.f;
#pragma unroll
    for (int i = 0; i < 8; i++) t += red[i];
    __syncthreads();
    return t;
}

__global__ void k_ln(const __nv_bfloat16* __restrict__ Ih, const __nv_bfloat16* __restrict__ Il,
                     const float* __restrict__ gw, const float* __restrict__ gb,
                     __nv_bfloat16* __restrict__ Oh, __nv_bfloat16* __restrict__ Ol)
{
    __shared__ float red[8];
    const int row = blockIdx.x;
    const int tid = threadIdx.x;
    const size_t base = (size_t)row * DIM;
    float x[4];
#pragma unroll
    for (int j = 0; j < 4; j++) {
        int c = tid + j * 256;
        x[j] = __bfloat162float(Ih[base + c]) + __bfloat162float(Il[base + c]);
    }
    float s = x[0] + x[1] + x[2] + x[3];
    float mu = blockSum256(s, red) * (1.0f / DIM);
    float d[4], s2 = 0.f;
#pragma unroll
    for (int j = 0; j < 4; j++) { d[j] = x[j] - mu; s2 += d[j] * d[j]; }
    float var = blockSum256(s2, red) * (1.0f / DIM);
    float inv = rsqrtf(var + 1e-5f);
#pragma unroll
    for (int j = 0; j < 4; j++) {
        int c = tid + j * 256;
        float y = d[j] * inv * gw[c] + gb[c];
        __nv_bfloat16 h, l;
        split1(y, h, l);
        Oh[base + c] = h;  Ol[base + c] = l;
    }
}

// ---------------- orchestration: 3-buffer rotation (R, A0, A1) ----------------
extern "C" void kernel_launch(void* const* d_in, const int* in_sizes, int n_in,
                              void* d_out, int out_size) {
    (void)in_sizes; (void)n_in; (void)out_size;
    const float* x     = (const float*)d_in[0];
    const float* scale = (const float*)d_in[1];
    const float* bias  = (const float*)d_in[2];
    const float* la    = (const float*)d_in[3];
    const float* lb    = (const float*)d_in[4];
    const float* lnw   = (const float*)d_in[5];
    const float* lnb   = (const float*)d_in[6];
    const int*   qw    = (const int*)d_in[7];

    __nv_bfloat16 *Wh, *Wl, *A0h, *A0l, *A1h, *A1l, *Rh, *Rl;
    cudaGetSymbolAddress((void**)&Wh,  g_Wh);
    cudaGetSymbolAddress((void**)&Wl,  g_Wl);
    cudaGetSymbolAddress((void**)&A0h, g_A0h);
    cudaGetSymbolAddress((void**)&A0l, g_A0l);
    cudaGetSymbolAddress((void**)&A1h, g_A1h);
    cudaGetSymbolAddress((void**)&A1l, g_A1l);
    cudaGetSymbolAddress((void**)&Rh,  g_Rh);
    cudaGetSymbolAddress((void**)&Rl,  g_Rl);

    cudaFuncSetAttribute(k_gemm<0>, cudaFuncAttributeMaxDynamicSharedMemorySize, SM_TOTAL);
    cudaFuncSetAttribute(k_gemm<1>, cudaFuncAttributeMaxDynamicSharedMemorySize, SM_TOTAL);
    cudaFuncSetAttribute(k_gemm<2>, cudaFuncAttributeMaxDynamicSharedMemorySize, SM_TOTAL);

    k_split<<<BATCH * DIM / 4 / 256, 256>>>(x, Rh, Rl);
    k_prep <<<NLAYERS * DIM * DIM / 2 / 256, 256>>>(qw, scale, la, lb);

    dim3 ggrid(DIM / BN, BATCH / BM);   // (8, 256)
    int li = 0;
    for (int blk = 0; blk < 6; ++blk) {
        // g0: R -> A0 (relu)
        const int W0 = li * DIM * DIM;
        k_gemm<0><<<ggrid, 256, SM_TOTAL>>>(Rh, Rl, Wh + W0, Wl + W0, bias + li * DIM,
                                            A0h, A0l, nullptr, nullptr, nullptr);
        li++;
        // g1: A0 -> A1 (relu)
        const int W1 = li * DIM * DIM;
        k_gemm<0><<<ggrid, 256, SM_TOTAL>>>(A0h, A0l, Wh + W1, Wl + W1, bias + li * DIM,
                                            A1h, A1l, nullptr, nullptr, nullptr);
        li++;
        // g2: A1 + R(residual) -> A0  (or d_out for last block)
        const int W2 = li * DIM * DIM;
        if (blk < 5) {
            k_gemm<1><<<ggrid, 256, SM_TOTAL>>>(A1h, A1l, Wh + W2, Wl + W2, bias + li * DIM,
                                                A0h, A0l, Rh, Rl, nullptr);
            li++;
            // LN: A0 -> R  (R doubles as next block's input AND residual)
            k_ln<<<BATCH, 256>>>(A0h, A0l, lnw + blk * DIM, lnb + blk * DIM, Rh, Rl);
        } else {
            k_gemm<2><<<ggrid, 256, SM_TOTAL>>>(A1h, A1l, Wh + W2, Wl + W2, bias + li * DIM,
                                                nullptr, nullptr, Rh, Rl, (float*)d_out);
            li++;
        }
    }
}

// round 13
// speedup vs baseline: 1.1966x; 1.1966x over previous
#include <cuda_runtime.h>
#include <cuda_bf16.h>
#include <cstdint>

#define DIM     1024
#define BATCH   16384
#define NLAYERS 18

// ---------------- GEMM tiling (R6 proven config) ----------------
#define BM 128
#define BN 128
#define BK 32                     // bf16 per K-chunk = 64B per row
#define NCHUNK (DIM / BK)         // 32

// smem stage: Ah/Al/Wh/Wl each 128 rows x 64B = 8KB -> stage 32KB, 2 stages = 64KB/CTA
#define OFF_AL 8192u
#define OFF_WH 16384u
#define OFF_WL 24576u
#define STAGE  32768u
#define SM_TOTAL (2 * 32768)

// ---------------- static device scratch ----------------
__device__ __align__(16) __nv_bfloat16 g_Wh[NLAYERS * DIM * DIM];
__device__ __align__(16) __nv_bfloat16 g_Wl[NLAYERS * DIM * DIM];
__device__ __align__(16) __nv_bfloat16 g_A0h[BATCH * DIM];
__device__ __align__(16) __nv_bfloat16 g_A0l[BATCH * DIM];
__device__ __align__(16) __nv_bfloat16 g_A1h[BATCH * DIM];
__device__ __align__(16) __nv_bfloat16 g_A1l[BATCH * DIM];
__device__ __align__(16) __nv_bfloat16 g_Rh [BATCH * DIM];
__device__ __align__(16) __nv_bfloat16 g_Rl [BATCH * DIM];

// ---------------- PTX helpers ----------------
__device__ __forceinline__ uint32_t smem_u32(const void* p) {
    uint32_t a;
    asm("{ .reg .u64 t; cvta.to.shared.u64 t, %1; cvt.u32.u64 %0, t; }" : "=r"(a) : "l"(p));
    return a;
}
#define CP_ASYNC16(dst, src) \
    asm volatile("cp.async.cg.shared.global [%0], [%1], 16;\n" :: "r"(dst), "l"(src))
#define CP_COMMIT() asm volatile("cp.async.commit_group;\n" ::: "memory")
#define CP_WAIT1()  asm volatile("cp.async.wait_group 1;\n" ::: "memory")
#define CP_WAIT0()  asm volatile("cp.async.wait_group 0;\n" ::: "memory")

#define LDSM_X4(r0, r1, r2, r3, addr) \
    asm volatile("ldmatrix.sync.aligned.m8n8.x4.shared.b16 {%0,%1,%2,%3}, [%4];\n" \
                 : "=r"(r0), "=r"(r1), "=r"(r2), "=r"(r3) : "r"(addr))

#define MMA4(d, a0, a1, a2, a3, b0, b1) \
    asm volatile("mma.sync.aligned.m16n8k16.row.col.f32.bf16.bf16.f32 " \
                 "{%0,%1,%2,%3},{%4,%5,%6,%7},{%8,%9},{%0,%1,%2,%3};\n" \
                 : "+f"((d)[0]), "+f"((d)[1]), "+f"((d)[2]), "+f"((d)[3]) \
                 : "r"(a0), "r"(a1), "r"(a2), "r"(a3), "r"(b0), "r"(b1))

// packed f32x2 helpers (used in k_prep; proven in R11)
#define PACK2(u, lo, hi) \
    asm volatile("mov.b64 %0, {%1, %2};\n" : "=l"(u) : "f"(lo), "f"(hi))
#define UNPACK2(lo, hi, u) \
    asm volatile("mov.b64 {%0, %1}, %2;\n" : "=f"(lo), "=f"(hi) : "l"(u))
#define FMA2(a, b, c) \
    asm volatile("fma.rn.f32x2 %0, %1, %2, %0;\n" : "+l"(a) : "l"(b), "l"(c))

__device__ __forceinline__ void split1(float v, __nv_bfloat16& h, __nv_bfloat16& l) {
    h = __float2bfloat16(v);
    l = __float2bfloat16(v - __bfloat162float(h));
}

// swizzle for 64B rows: 16B-group g XOR (row & 3) — verified conflict-free (R6/R11)
__device__ __forceinline__ uint32_t swz64(uint32_t row, uint32_t g16) {
    return row * 64u + ((g16 ^ (row & 3u)) << 4);
}

// stage loader: 32KB / 256 threads = 8 cp.async x16B per thread
__device__ __forceinline__ void load_chunk(
    uint32_t st, int c, int tid,
    const char* pAh, const char* pAl, const char* pWh, const char* pWl)
{
    const size_t koff = (size_t)c * 64u;
#pragma unroll
    for (int i = 0; i < 8; i++) {
        int idx = tid + i * 256;          // 0..2047
        int arr = idx >> 9;               // 0..3 : Ah, Al, Wh, Wl
        int r   = (idx >> 2) & 127;       // row 0..127
        int g   = idx & 3;                // 16B group 0..3
        const char* base = (arr == 0) ? pAh : (arr == 1) ? pAl : (arr == 2) ? pWh : pWl;
        const char* src = base + (size_t)r * 2048 + koff + (size_t)(g * 16);
        uint32_t dst = st + (uint32_t)arr * 8192u + swz64((uint32_t)r, (uint32_t)g);
        CP_ASYNC16(dst, src);
    }
    CP_COMMIT();
}

// ---------------- fused GEMM layer (R6 exact) ----------------
// C[BM,BN] = A[BM,K] * W[BN,K]^T, 3-term bf16 split, fp32 accum.
// MODE 0: relu(C+bias)->bf16 pair | MODE 1: C+bias+res->bf16 pair | MODE 2: C+bias+res->fp32
template<int MODE>
__global__ void __launch_bounds__(256, 2)
k_gemm(const __nv_bfloat16* __restrict__ Ah, const __nv_bfloat16* __restrict__ Al,
       const __nv_bfloat16* __restrict__ Wh, const __nv_bfloat16* __restrict__ Wl,
       const float* __restrict__ bias,
       __nv_bfloat16* __restrict__ Oh, __nv_bfloat16* __restrict__ Ol,
       const __nv_bfloat16* __restrict__ Rh, const __nv_bfloat16* __restrict__ Rl,
       float* __restrict__ Of)
{
    extern __shared__ char smem[];
    const uint32_t sb = smem_u32(smem);
    const int tid = threadIdx.x, wid = tid >> 5, lane = tid & 31;
    const int Mb = blockIdx.y * BM, Nb = blockIdx.x * BN;
    const int wm = (wid & 1) * 64;          // 2 m-warps
    const int wn = (wid >> 1) * 32;         // 4 n-warps

    const char* pAh = (const char*)(Ah + (size_t)Mb * DIM);
    const char* pAl = (const char*)(Al + (size_t)Mb * DIM);
    const char* pWh = (const char*)(Wh + (size_t)Nb * DIM);
    const char* pWl = (const char*)(Wl + (size_t)Nb * DIM);

    const int l7  = lane & 7;
    const int l15 = lane & 15;
    const int lhi = lane >> 4;              // 0/1
    const int lb8 = ((lane >> 3) & 1) << 3;

    uint32_t adA[2][4], adB[2][2];
#pragma unroll
    for (int kk = 0; kk < 2; kk++) {
#pragma unroll
        for (int mi = 0; mi < 4; mi++) {
            uint32_t r = (uint32_t)(wm + mi * 16 + l15);
            adA[kk][mi] = swz64(r, (uint32_t)(2 * kk + lhi));
        }
#pragma unroll
        for (int j = 0; j < 2; j++) {
            uint32_t r = (uint32_t)(wn + j * 16 + l7 + lb8);
            adB[kk][j] = swz64(r, (uint32_t)(2 * kk + lhi));
        }
    }

    float acc[4][4][4];
#pragma unroll
    for (int mi = 0; mi < 4; mi++)
#pragma unroll
        for (int ni = 0; ni < 4; ni++)
#pragma unroll
            for (int k = 0; k < 4; k++) acc[mi][ni][k] = 0.f;

    load_chunk(sb, 0, tid, pAh, pAl, pWh, pWl);

#pragma unroll 1
    for (int c = 0; c < NCHUNK; c++) {
        const uint32_t st = sb + (uint32_t)(c & 1) * STAGE;
        if (c + 1 < NCHUNK) {
            load_chunk(sb + (uint32_t)((c + 1) & 1) * STAGE, c + 1, tid, pAh, pAl, pWh, pWl);
            CP_WAIT1();
        } else {
            CP_WAIT0();
        }
        __syncthreads();

        const uint32_t stAh = st, stAl = st + OFF_AL, stWh = st + OFF_WH, stWl = st + OFF_WL;
#pragma unroll
        for (int kk = 0; kk < 2; kk++) {
            uint32_t aH[4][4], bH[2][4];
#pragma unroll
            for (int mi = 0; mi < 4; mi++)
                LDSM_X4(aH[mi][0], aH[mi][1], aH[mi][2], aH[mi][3], stAh + adA[kk][mi]);
#pragma unroll
            for (int j = 0; j < 2; j++)
                LDSM_X4(bH[j][0], bH[j][1], bH[j][2], bH[j][3], stWh + adB[kk][j]);
            // T1: Ah*Wh
#pragma unroll
            for (int mi = 0; mi < 4; mi++)
#pragma unroll
                for (int j = 0; j < 2; j++) {
                    MMA4(acc[mi][2 * j],     aH[mi][0], aH[mi][1], aH[mi][2], aH[mi][3], bH[j][0], bH[j][2]);
                    MMA4(acc[mi][2 * j + 1], aH[mi][0], aH[mi][1], aH[mi][2], aH[mi][3], bH[j][1], bH[j][3]);
                }
            // T3: Al*Wh (bH live)
            {
                uint32_t aL[4][4];
#pragma unroll
                for (int mi = 0; mi < 4; mi++)
                    LDSM_X4(aL[mi][0], aL[mi][1], aL[mi][2], aL[mi][3], stAl + adA[kk][mi]);
#pragma unroll
                for (int mi = 0; mi < 4; mi++)
#pragma unroll
                    for (int j = 0; j < 2; j++) {
                        MMA4(acc[mi][2 * j],     aL[mi][0], aL[mi][1], aL[mi][2], aL[mi][3], bH[j][0], bH[j][2]);
                        MMA4(acc[mi][2 * j + 1], aL[mi][0], aL[mi][1], aL[mi][2], aL[mi][3], bH[j][1], bH[j][3]);
                    }
            }
            // T2: Ah*Wl (aH live)
            {
                uint32_t bL[2][4];
#pragma unroll
                for (int j = 0; j < 2; j++)
                    LDSM_X4(bL[j][0], bL[j][1], bL[j][2], bL[j][3], stWl + adB[kk][j]);
#pragma unroll
                for (int mi = 0; mi < 4; mi++)
#pragma unroll
                    for (int j = 0; j < 2; j++) {
                        MMA4(acc[mi][2 * j],     aH[mi][0], aH[mi][1], aH[mi][2], aH[mi][3], bL[j][0], bL[j][2]);
                        MMA4(acc[mi][2 * j + 1], aH[mi][0], aH[mi][1], aH[mi][2], aH[mi][3], bL[j][1], bL[j][3]);
                    }
            }
        }
        __syncthreads();
    }

    // ---- epilogue (verified fragment layout) ----
    auto emit = [&](int r, int c, float v0, float v1) {
        size_t off = (size_t)r * DIM + c;
        if (MODE >= 1) {
            __nv_bfloat162 rh2 = *reinterpret_cast<const __nv_bfloat162*>(Rh + off);
            __nv_bfloat162 rl2 = *reinterpret_cast<const __nv_bfloat162*>(Rl + off);
            v0 += __bfloat162float(rh2.x) + __bfloat162float(rl2.x);
            v1 += __bfloat162float(rh2.y) + __bfloat162float(rl2.y);
        }
        if (MODE == 0) { v0 = fmaxf(v0, 0.f); v1 = fmaxf(v1, 0.f); }
        if (MODE == 2) {
            *reinterpret_cast<float2*>(Of + off) = make_float2(v0, v1);
        } else {
            __nv_bfloat16 h0, l0, h1, l1;
            split1(v0, h0, l0); split1(v1, h1, l1);
            __nv_bfloat162 H; H.x = h0; H.y = h1;
            __nv_bfloat162 L; L.x = l0; L.y = l1;
            *reinterpret_cast<__nv_bfloat162*>(Oh + off) = H;
            *reinterpret_cast<__nv_bfloat162*>(Ol + off) = L;
        }
    };

    const int g  = lane >> 2;
    const int tg = lane & 3;
#pragma unroll
    for (int mi = 0; mi < 4; mi++) {
#pragma unroll
        for (int ni = 0; ni < 4; ni++) {
            int r0 = Mb + wm + mi * 16 + g;
            int c0 = Nb + wn + ni * 8 + tg * 2;
            float b0 = __ldg(bias + c0), b1 = __ldg(bias + c0 + 1);
            emit(r0,     c0, acc[mi][ni][0] + b0, acc[mi][ni][1] + b1);
            emit(r0 + 8, c0, acc[mi][ni][2] + b0, acc[mi][ni][3] + b1);
        }
    }
}

// ---------------- split input x into (hi,lo) pair in R only ----------------
__global__ void k_split(const float* __restrict__ x,
                        __nv_bfloat16* __restrict__ rh, __nv_bfloat16* __restrict__ rl) {
    int i4 = blockIdx.x * blockDim.x + threadIdx.x;
    float4 v = reinterpret_cast<const float4*>(x)[i4];
    __nv_bfloat16 h0,h1,h2,h3,l0,l1,l2,l3;
    split1(v.x,h0,l0); split1(v.y,h1,l1); split1(v.z,h2,l2); split1(v.w,h3,l3);
    __nv_bfloat162 H0; H0.x=h0; H0.y=h1;
    __nv_bfloat162 H1; H1.x=h2; H1.y=h3;
    __nv_bfloat162 L0; L0.x=l0; L0.y=l1;
    __nv_bfloat162 L1; L1.x=l2; L1.y=l3;
    __nv_bfloat162* RH = reinterpret_cast<__nv_bfloat162*>(rh);
    __nv_bfloat162* RL = reinterpret_cast<__nv_bfloat162*>(rl);
    int b = i4 * 2;
    RH[b] = H0; RH[b+1] = H1;
    RL[b] = L0; RL[b+1] = L1;
}

// ---------------- dequant + fold LoRA (f32x2, 2 outputs/thread; R11 proven) ----------------
__global__ void __launch_bounds__(256)
k_prep(const int* __restrict__ qw, const float* __restrict__ scale,
       const float* __restrict__ la, const float* __restrict__ lb) {
    int idx2 = blockIdx.x * 256 + threadIdx.x;        // < 18*1024*512
    int l    = idx2 >> 19;
    int rem  = idx2 & 0x7FFFF;
    int o    = rem >> 9;
    int i    = (rem & 511) * 2;

    size_t base = ((size_t)l << 20) + ((size_t)o << 10) + (size_t)i;
    int2 q2 = *reinterpret_cast<const int2*>(qw + base);
    float s = scale[(l << 16) + (o << 6) + (i >> 4)];
    float w0 = ((float)q2.x / 15.0f * 2.0f - 1.0f) * s;
    float w1 = ((float)q2.y / 15.0f * 2.0f - 1.0f) * s;

    const float4* lb4 = reinterpret_cast<const float4*>(lb + l * (DIM * 32) + o * 32);
    float lbv[32];
#pragma unroll
    for (int q = 0; q < 8; q++) {
        float4 v = lb4[q];
        lbv[q * 4]     = v.x; lbv[q * 4 + 1] = v.y;
        lbv[q * 4 + 2] = v.z; lbv[q * 4 + 3] = v.w;
    }

    const float* lar = la + l * (32 * DIM) + i;
    unsigned long long accp;
    PACK2(accp, w0, w1);
#pragma unroll
    for (int r = 0; r < 32; r++) {
        float2 a2 = *reinterpret_cast<const float2*>(lar + (size_t)r * DIM);
        unsigned long long ap, bp;
        PACK2(ap, a2.x, a2.y);
        PACK2(bp, lbv[r], lbv[r]);
        FMA2(accp, bp, ap);
    }
    float r0, r1;
    UNPACK2(r0, r1, accp);

    __nv_bfloat16 h0, l0, h1, l1;
    split1(r0, h0, l0);
    split1(r1, h1, l1);
    __nv_bfloat162 H; H.x = h0; H.y = h1;
    __nv_bfloat162 L; L.x = l0; L.y = l1;
    *reinterpret_cast<__nv_bfloat162*>(g_Wh + base) = H;
    *reinterpret_cast<__nv_bfloat162*>(g_Wl + base) = L;
}

// ---------------- LayerNorm: vectorized uint2 (4 bf16) accesses ----------------
__device__ __forceinline__ float blockSum256(float v, float* red) {
#pragma unroll
    for (int o = 16; o > 0; o >>= 1) v += __shfl_xor_sync(0xffffffffu, v, o);
    int w = threadIdx.x >> 5;
    if ((threadIdx.x & 31) == 0) red[w] = v;
    __syncthreads();
    float t = 0.f;
#pragma unroll
    for (int i = 0; i < 8; i++) t += red[i];
    __syncthreads();
    return t;
}

__global__ void k_ln(const __nv_bfloat16* __restrict__ Ih, const __nv_bfloat16* __restrict__ Il,
                     const float* __restrict__ gw, const float* __restrict__ gb,
                     __nv_bfloat16* __restrict__ Oh, __nv_bfloat16* __restrict__ Ol)
{
    __shared__ float red[8];
    const int row = blockIdx.x;
    const int tid = threadIdx.x;
    const size_t base = (size_t)row * DIM;
    const int c0 = tid * 4;                       // cols [c0, c0+4)

    // vector loads: 4 bf16 = 8 bytes per array
    uint2 hv = *reinterpret_cast<const uint2*>(Ih + base + c0);
    uint2 lv = *reinterpret_cast<const uint2*>(Il + base + c0);
    const __nv_bfloat162* hp = reinterpret_cast<const __nv_bfloat162*>(&hv);
    const __nv_bfloat162* lp = reinterpret_cast<const __nv_bfloat162*>(&lv);
    float x[4];
    x[0] = __bfloat162float(hp[0].x) + __bfloat162float(lp[0].x);
    x[1] = __bfloat162float(hp[0].y) + __bfloat162float(lp[0].y);
    x[2] = __bfloat162float(hp[1].x) + __bfloat162float(lp[1].x);
    x[3] = __bfloat162float(hp[1].y) + __bfloat162float(lp[1].y);

    float s = x[0] + x[1] + x[2] + x[3];
    float mu = blockSum256(s, red) * (1.0f / DIM);
    float d[4], s2 = 0.f;
#pragma unroll
    for (int j = 0; j < 4; j++) { d[j] = x[j] - mu; s2 += d[j] * d[j]; }
    float var = blockSum256(s2, red) * (1.0f / DIM);
    float inv = rsqrtf(var + 1e-5f);

    float4 gwv = *reinterpret_cast<const float4*>(gw + c0);
    float4 gbv = *reinterpret_cast<const float4*>(gb + c0);
    float y[4];
    y[0] = d[0] * inv * gwv.x + gbv.x;
    y[1] = d[1] * inv * gwv.y + gbv.y;
    y[2] = d[2] * inv * gwv.z + gbv.z;
    y[3] = d[3] * inv * gwv.w + gbv.w;

    uint2 ho, lo;
    __nv_bfloat162* hop = reinterpret_cast<__nv_bfloat162*>(&ho);
    __nv_bfloat162* lop = reinterpret_cast<__nv_bfloat162*>(&lo);
#pragma unroll
    for (int j = 0; j < 2; j++) {
        __nv_bfloat16 h0, l0, h1, l1;
        split1(y[j * 2], h0, l0);
        split1(y[j * 2 + 1], h1, l1);
        __nv_bfloat162 H; H.x = h0; H.y = h1;
        __nv_bfloat162 L; L.x = l0; L.y = l1;
        hop[j] = H; lop[j] = L;
    }
    *reinterpret_cast<uint2*>(Oh + base + c0) = ho;
    *reinterpret_cast<uint2*>(Ol + base + c0) = lo;
}

// ---------------- orchestration: 3-buffer rotation (R, A0, A1) ----------------
extern "C" void kernel_launch(void* const* d_in, const int* in_sizes, int n_in,
                              void* d_out, int out_size) {
    (void)in_sizes; (void)n_in; (void)out_size;
    const float* x     = (const float*)d_in[0];
    const float* scale = (const float*)d_in[1];
    const float* bias  = (const float*)d_in[2];
    const float* la    = (const float*)d_in[3];
    const float* lb    = (const float*)d_in[4];
    const float* lnw   = (const float*)d_in[5];
    const float* lnb   = (const float*)d_in[6];
    const int*   qw    = (const int*)d_in[7];

    __nv_bfloat16 *Wh, *Wl, *A0h, *A0l, *A1h, *A1l, *Rh, *Rl;
    cudaGetSymbolAddress((void**)&Wh,  g_Wh);
    cudaGetSymbolAddress((void**)&Wl,  g_Wl);
    cudaGetSymbolAddress((void**)&A0h, g_A0h);
    cudaGetSymbolAddress((void**)&A0l, g_A0l);
    cudaGetSymbolAddress((void**)&A1h, g_A1h);
    cudaGetSymbolAddress((void**)&A1l, g_A1l);
    cudaGetSymbolAddress((void**)&Rh,  g_Rh);
    cudaGetSymbolAddress((void**)&Rl,  g_Rl);

    cudaFuncSetAttribute(k_gemm<0>, cudaFuncAttributeMaxDynamicSharedMemorySize, SM_TOTAL);
    cudaFuncSetAttribute(k_gemm<1>, cudaFuncAttributeMaxDynamicSharedMemorySize, SM_TOTAL);
    cudaFuncSetAttribute(k_gemm<2>, cudaFuncAttributeMaxDynamicSharedMemorySize, SM_TOTAL);

    k_split<<<BATCH * DIM / 4 / 256, 256>>>(x, Rh, Rl);
    k_prep <<<NLAYERS * DIM * DIM / 2 / 256, 256>>>(qw, scale, la, lb);

    dim3 ggrid(DIM / BN, BATCH / BM);   // (8, 128)
    int li = 0;
    for (int blk = 0; blk < 6; ++blk) {
        // g0: R -> A0 (relu)
        const int W0 = li * DIM * DIM;
        k_gemm<0><<<ggrid, 256, SM_TOTAL>>>(Rh, Rl, Wh + W0, Wl + W0, bias + li * DIM,
                                            A0h, A0l, nullptr, nullptr, nullptr);
        li++;
        // g1: A0 -> A1 (relu)
        const int W1 = li * DIM * DIM;
        k_gemm<0><<<ggrid, 256, SM_TOTAL>>>(A0h, A0l, Wh + W1, Wl + W1, bias + li * DIM,
                                            A1h, A1l, nullptr, nullptr, nullptr);
        li++;
        // g2: A1 + R(residual) -> A0  (or d_out for last block)
        const int W2 = li * DIM * DIM;
        if (blk < 5) {
            k_gemm<1><<<ggrid, 256, SM_TOTAL>>>(A1h, A1l, Wh + W2, Wl + W2, bias + li * DIM,
                                                A0h, A0l, Rh, Rl, nullptr);
            li++;
            // LN: A0 -> R  (R doubles as next block's input AND residual)
            k_ln<<<BATCH, 256>>>(A0h, A0l, lnw + blk * DIM, lnb + blk * DIM, Rh, Rl);
        } else {
            k_gemm<2><<<ggrid, 256, SM_TOTAL>>>(A1h, A1l, Wh + W2, Wl + W2, bias + li * DIM,
                                                nullptr, nullptr, Rh, Rl, (float*)d_out);
            li++;
        }
    }
}

// round 14
// speedup vs baseline: 2.6058x; 2.1776x over previous
#include <cuda_runtime.h>
#include <cuda_fp16.h>
#include <cstdint>

#define DIM     1024
#define BATCH   16384
#define NLAYERS 18

// ---------------- GEMM tiling (R6 structure, single fp16 operands) ----------------
#define BM 128
#define BN 128
#define BK 32                     // fp16 per K-chunk = 64B per row
#define NCHUNK (DIM / BK)         // 32

// smem stage: X 128x64B = 8KB, W 128x64B = 8KB -> stage 16KB, 2 stages = 32KB/CTA
#define OFF_W  8192u
#define STAGE  16384u
#define SM_TOTAL (2 * 16384)

// ---------------- static device scratch ----------------
__device__ __align__(16) __half g_W  [NLAYERS * DIM * DIM];
__device__ __align__(16) __half g_A0 [BATCH * DIM];
__device__ __align__(16) __half g_A1 [BATCH * DIM];
__device__ __align__(16) __half g_R  [BATCH * DIM];

// ---------------- PTX helpers ----------------
__device__ __forceinline__ uint32_t smem_u32(const void* p) {
    uint32_t a;
    asm("{ .reg .u64 t; cvta.to.shared.u64 t, %1; cvt.u32.u64 %0, t; }" : "=r"(a) : "l"(p));
    return a;
}
#define CP_ASYNC16(dst, src) \
    asm volatile("cp.async.cg.shared.global [%0], [%1], 16;\n" :: "r"(dst), "l"(src))
#define CP_COMMIT() asm volatile("cp.async.commit_group;\n" ::: "memory")
#define CP_WAIT1()  asm volatile("cp.async.wait_group 1;\n" ::: "memory")
#define CP_WAIT0()  asm volatile("cp.async.wait_group 0;\n" ::: "memory")

#define LDSM_X4(r0, r1, r2, r3, addr) \
    asm volatile("ldmatrix.sync.aligned.m8n8.x4.shared.b16 {%0,%1,%2,%3}, [%4];\n" \
                 : "=r"(r0), "=r"(r1), "=r"(r2), "=r"(r3) : "r"(addr))

#define MMA4(d, a0, a1, a2, a3, b0, b1) \
    asm volatile("mma.sync.aligned.m16n8k16.row.col.f32.f16.f16.f32 " \
                 "{%0,%1,%2,%3},{%4,%5,%6,%7},{%8,%9},{%0,%1,%2,%3};\n" \
                 : "+f"((d)[0]), "+f"((d)[1]), "+f"((d)[2]), "+f"((d)[3]) \
                 : "r"(a0), "r"(a1), "r"(a2), "r"(a3), "r"(b0), "r"(b1))

// packed f32x2 helpers (k_prep inner loop; proven R11)
#define PACK2(u, lo, hi) \
    asm volatile("mov.b64 %0, {%1, %2};\n" : "=l"(u) : "f"(lo), "f"(hi))
#define UNPACK2(lo, hi, u) \
    asm volatile("mov.b64 {%0, %1}, %2;\n" : "=f"(lo), "=f"(hi) : "l"(u))
#define FMA2(a, b, c) \
    asm volatile("fma.rn.f32x2 %0, %1, %2, %0;\n" : "+l"(a) : "l"(b), "l"(c))

// swizzle for 64B rows: 16B-group g XOR (row & 3) — verified conflict-free (R6..R13)
__device__ __forceinline__ uint32_t swz64(uint32_t row, uint32_t g16) {
    return row * 64u + ((g16 ^ (row & 3u)) << 4);
}

// stage loader: 16KB / 256 threads = 4 cp.async x16B per thread
__device__ __forceinline__ void load_chunk(
    uint32_t st, int c, int tid, const char* pX, const char* pW)
{
    const size_t koff = (size_t)c * 64u;
#pragma unroll
    for (int i = 0; i < 4; i++) {
        int idx = tid + i * 256;          // 0..1023
        int arr = idx >> 9;               // 0: X, 1: W
        int r   = (idx >> 2) & 127;       // row 0..127
        int g   = idx & 3;                // 16B group 0..3
        const char* base = arr ? pW : pX;
        uint32_t dst = st + (uint32_t)arr * OFF_W + swz64((uint32_t)r, (uint32_t)g);
        CP_ASYNC16(dst, base + (size_t)r * 2048 + koff + (size_t)(g * 16));
    }
    CP_COMMIT();
}

// ---------------- fused GEMM layer: single fp16 x single fp16, fp32 accum ----------------
// MODE 0: relu(C+bias)->fp16 | MODE 1: C+bias+res->fp16 | MODE 2: C+bias+res->fp32
template<int MODE>
__global__ void __launch_bounds__(256, 2)
k_gemm(const __half* __restrict__ X, const __half* __restrict__ W,
       const float* __restrict__ bias,
       __half* __restrict__ O,
       const __half* __restrict__ R,
       float* __restrict__ Of)
{
    extern __shared__ char smem[];
    const uint32_t sb = smem_u32(smem);
    const int tid = threadIdx.x, wid = tid >> 5, lane = tid & 31;
    const int Mb = blockIdx.y * BM, Nb = blockIdx.x * BN;
    const int wm = (wid & 1) * 64;          // 2 m-warps
    const int wn = (wid >> 1) * 32;         // 4 n-warps

    const char* pX = (const char*)(X + (size_t)Mb * DIM);
    const char* pW = (const char*)(W + (size_t)Nb * DIM);

    const int l7  = lane & 7;
    const int l15 = lane & 15;
    const int lhi = lane >> 4;              // 0/1
    const int lb8 = ((lane >> 3) & 1) << 3;

    uint32_t adA[2][4], adB[2][2];
#pragma unroll
    for (int kk = 0; kk < 2; kk++) {
#pragma unroll
        for (int mi = 0; mi < 4; mi++) {
            uint32_t r = (uint32_t)(wm + mi * 16 + l15);
            adA[kk][mi] = swz64(r, (uint32_t)(2 * kk + lhi));
        }
#pragma unroll
        for (int j = 0; j < 2; j++) {
            uint32_t r = (uint32_t)(wn + j * 16 + l7 + lb8);
            adB[kk][j] = swz64(r, (uint32_t)(2 * kk + lhi));
        }
    }

    float acc[4][4][4];
#pragma unroll
    for (int mi = 0; mi < 4; mi++)
#pragma unroll
        for (int ni = 0; ni < 4; ni++)
#pragma unroll
            for (int k = 0; k < 4; k++) acc[mi][ni][k] = 0.f;

    load_chunk(sb, 0, tid, pX, pW);

#pragma unroll 1
    for (int c = 0; c < NCHUNK; c++) {
        const uint32_t st = sb + (uint32_t)(c & 1) * STAGE;
        if (c + 1 < NCHUNK) {
            load_chunk(sb + (uint32_t)((c + 1) & 1) * STAGE, c + 1, tid, pX, pW);
            CP_WAIT1();
        } else {
            CP_WAIT0();
        }
        __syncthreads();

        const uint32_t stX = st, stW = st + OFF_W;
#pragma unroll
        for (int kk = 0; kk < 2; kk++) {
            uint32_t aF[4][4], bF[2][4];
#pragma unroll
            for (int mi = 0; mi < 4; mi++)
                LDSM_X4(aF[mi][0], aF[mi][1], aF[mi][2], aF[mi][3], stX + adA[kk][mi]);
#pragma unroll
            for (int j = 0; j < 2; j++)
                LDSM_X4(bF[j][0], bF[j][1], bF[j][2], bF[j][3], stW + adB[kk][j]);
#pragma unroll
            for (int mi = 0; mi < 4; mi++)
#pragma unroll
                for (int j = 0; j < 2; j++) {
                    MMA4(acc[mi][2 * j],     aF[mi][0], aF[mi][1], aF[mi][2], aF[mi][3], bF[j][0], bF[j][2]);
                    MMA4(acc[mi][2 * j + 1], aF[mi][0], aF[mi][1], aF[mi][2], aF[mi][3], bF[j][1], bF[j][3]);
                }
        }
        __syncthreads();
    }

    // ---- epilogue ----
    auto emit = [&](int r, int c, float v0, float v1) {
        size_t off = (size_t)r * DIM + c;
        if (MODE >= 1) {
            __half2 r2 = *reinterpret_cast<const __half2*>(R + off);
            v0 += __half2float(r2.x);
            v1 += __half2float(r2.y);
        }
        if (MODE == 0) { v0 = fmaxf(v0, 0.f); v1 = fmaxf(v1, 0.f); }
        if (MODE == 2) {
            *reinterpret_cast<float2*>(Of + off) = make_float2(v0, v1);
        } else {
            __half2 h2; h2.x = __float2half(v0); h2.y = __float2half(v1);
            *reinterpret_cast<__half2*>(O + off) = h2;
        }
    };

    const int g  = lane >> 2;
    const int tg = lane & 3;
#pragma unroll
    for (int mi = 0; mi < 4; mi++) {
#pragma unroll
        for (int ni = 0; ni < 4; ni++) {
            int r0 = Mb + wm + mi * 16 + g;
            int c0 = Nb + wn + ni * 8 + tg * 2;
            float b0 = __ldg(bias + c0), b1 = __ldg(bias + c0 + 1);
            emit(r0,     c0, acc[mi][ni][0] + b0, acc[mi][ni][1] + b1);
            emit(r0 + 8, c0, acc[mi][ni][2] + b0, acc[mi][ni][3] + b1);
        }
    }
}

// ---------------- split input x -> fp16 in R ----------------
__global__ void k_split(const float* __restrict__ x, __half* __restrict__ r) {
    int i4 = blockIdx.x * blockDim.x + threadIdx.x;
    float4 v = reinterpret_cast<const float4*>(x)[i4];
    __half2 h0; h0.x = __float2half(v.x); h0.y = __float2half(v.y);
    __half2 h1; h1.x = __float2half(v.z); h1.y = __float2half(v.w);
    __half2* R2 = reinterpret_cast<__half2*>(r);
    R2[i4 * 2]     = h0;
    R2[i4 * 2 + 1] = h1;
}

// ---------------- dequant + fold LoRA -> fp16 W (2 outputs/thread) ----------------
__global__ void __launch_bounds__(256)
k_prep(const int* __restrict__ qw, const float* __restrict__ scale,
       const float* __restrict__ la, const float* __restrict__ lb) {
    int idx2 = blockIdx.x * 256 + threadIdx.x;        // < 18*1024*512
    int l    = idx2 >> 19;
    int rem  = idx2 & 0x7FFFF;
    int o    = rem >> 9;
    int i    = (rem & 511) * 2;

    size_t base = ((size_t)l << 20) + ((size_t)o << 10) + (size_t)i;
    int2 q2 = *reinterpret_cast<const int2*>(qw + base);
    float s = scale[(l << 16) + (o << 6) + (i >> 4)];
    float w0 = ((float)q2.x / 15.0f * 2.0f - 1.0f) * s;
    float w1 = ((float)q2.y / 15.0f * 2.0f - 1.0f) * s;

    const float4* lb4 = reinterpret_cast<const float4*>(lb + l * (DIM * 32) + o * 32);
    float lbv[32];
#pragma unroll
    for (int q = 0; q < 8; q++) {
        float4 v = lb4[q];
        lbv[q * 4]     = v.x; lbv[q * 4 + 1] = v.y;
        lbv[q * 4 + 2] = v.z; lbv[q * 4 + 3] = v.w;
    }

    const float* lar = la + l * (32 * DIM) + i;
    unsigned long long accp;
    PACK2(accp, w0, w1);
#pragma unroll
    for (int r = 0; r < 32; r++) {
        float2 a2 = *reinterpret_cast<const float2*>(lar + (size_t)r * DIM);
        unsigned long long ap, bp;
        PACK2(ap, a2.x, a2.y);
        PACK2(bp, lbv[r], lbv[r]);
        FMA2(accp, bp, ap);
    }
    float r0, r1;
    UNPACK2(r0, r1, accp);

    __half2 h2; h2.x = __float2half(r0); h2.y = __float2half(r1);
    *reinterpret_cast<__half2*>(g_W + base) = h2;
}

// ---------------- LayerNorm (fp16 in/out, vectorized) ----------------
__device__ __forceinline__ float blockSum256(float v, float* red) {
#pragma unroll
    for (int o = 16; o > 0; o >>= 1) v += __shfl_xor_sync(0xffffffffu, v, o);
    int w = threadIdx.x >> 5;
    if ((threadIdx.x & 31) == 0) red[w] = v;
    __syncthreads();
    float t = 0.f;
#pragma unroll
    for (int i = 0; i < 8; i++) t += red[i];
    __syncthreads();
    return t;
}

__global__ void k_ln(const __half* __restrict__ I,
                     const float* __restrict__ gw, const float* __restrict__ gb,
                     __half* __restrict__ O)
{
    __shared__ float red[8];
    const int row = blockIdx.x;
    const int tid = threadIdx.x;
    const size_t base = (size_t)row * DIM;
    const int c0 = tid * 4;

    uint2 iv = *reinterpret_cast<const uint2*>(I + base + c0);
    const __half2* ip = reinterpret_cast<const __half2*>(&iv);
    float x[4];
    x[0] = __half2float(ip[0].x);
    x[1] = __half2float(ip[0].y);
    x[2] = __half2float(ip[1].x);
    x[3] = __half2float(ip[1].y);

    float s = x[0] + x[1] + x[2] + x[3];
    float mu = blockSum256(s, red) * (1.0f / DIM);
    float d[4], s2 = 0.f;
#pragma unroll
    for (int j = 0; j < 4; j++) { d[j] = x[j] - mu; s2 += d[j] * d[j]; }
    float var = blockSum256(s2, red) * (1.0f / DIM);
    float inv = rsqrtf(var + 1e-5f);

    float4 gwv = *reinterpret_cast<const float4*>(gw + c0);
    float4 gbv = *reinterpret_cast<const float4*>(gb + c0);
    float y0 = d[0] * inv * gwv.x + gbv.x;
    float y1 = d[1] * inv * gwv.y + gbv.y;
    float y2 = d[2] * inv * gwv.z + gbv.z;
    float y3 = d[3] * inv * gwv.w + gbv.w;

    uint2 ov;
    __half2* op = reinterpret_cast<__half2*>(&ov);
    op[0].x = __float2half(y0); op[0].y = __float2half(y1);
    op[1].x = __float2half(y2); op[1].y = __float2half(y3);
    *reinterpret_cast<uint2*>(O + base + c0) = ov;
}

// ---------------- orchestration: 3-buffer rotation (R, A0, A1) ----------------
extern "C" void kernel_launch(void* const* d_in, const int* in_sizes, int n_in,
                              void* d_out, int out_size) {
    (void)in_sizes; (void)n_in; (void)out_size;
    const float* x     = (const float*)d_in[0];
    const float* scale = (const float*)d_in[1];
    const float* bias  = (const float*)d_in[2];
    const float* la    = (const float*)d_in[3];
    const float* lb    = (const float*)d_in[4];
    const float* lnw   = (const float*)d_in[5];
    const float* lnb   = (const float*)d_in[6];
    const int*   qw    = (const int*)d_in[7];

    __half *W, *A0, *A1, *R;
    cudaGetSymbolAddress((void**)&W,  g_W);
    cudaGetSymbolAddress((void**)&A0, g_A0);
    cudaGetSymbolAddress((void**)&A1, g_A1);
    cudaGetSymbolAddress((void**)&R,  g_R);

    cudaFuncSetAttribute(k_gemm<0>, cudaFuncAttributeMaxDynamicSharedMemorySize, SM_TOTAL);
    cudaFuncSetAttribute(k_gemm<1>, cudaFuncAttributeMaxDynamicSharedMemorySize, SM_TOTAL);
    cudaFuncSetAttribute(k_gemm<2>, cudaFuncAttributeMaxDynamicSharedMemorySize, SM_TOTAL);

    k_split<<<BATCH * DIM / 4 / 256, 256>>>(x, R);
    k_prep <<<NLAYERS * DIM * DIM / 2 / 256, 256>>>(qw, scale, la, lb);

    dim3 ggrid(DIM / BN, BATCH / BM);   // (8, 128)
    int li = 0;
    for (int blk = 0; blk < 6; ++blk) {
        // g0: R -> A0 (relu)
        const int W0 = li * DIM * DIM;
        k_gemm<0><<<ggrid, 256, SM_TOTAL>>>(R, W + W0, bias + li * DIM, A0, nullptr, nullptr);
        li++;
        // g1: A0 -> A1 (relu)
        const int W1 = li * DIM * DIM;
        k_gemm<0><<<ggrid, 256, SM_TOTAL>>>(A0, W + W1, bias + li * DIM, A1, nullptr, nullptr);
        li++;
        // g2: A1 + R(residual) -> A0  (or d_out for last block)
        const int W2 = li * DIM * DIM;
        if (blk < 5) {
            k_gemm<1><<<ggrid, 256, SM_TOTAL>>>(A1, W + W2, bias + li * DIM, A0, R, nullptr);
            li++;
            // LN: A0 -> R  (R doubles as next block's input AND residual)
            k_ln<<<BATCH, 256>>>(A0, lnw + blk * DIM, lnb + blk * DIM, R);
        } else {
            k_gemm<2><<<ggrid, 256, SM_TOTAL>>>(A1, W + W2, bias + li * DIM,
                                                nullptr, R, (float*)d_out);
            li++;
        }
    }
}